// round 4
// baseline (speedup 1.0000x reference)
#include <cuda_runtime.h>

typedef unsigned long long u64;

// ---------------- f32x2 helpers (sm_100+) ----------------
__device__ __forceinline__ u64 pack2(float x) {
    u64 r;
    asm("mov.b64 %0, {%1, %1};" : "=l"(r) : "f"(x));
    return r;
}
__device__ __forceinline__ u64 pack2f(float lo, float hi) {
    u64 r;
    asm("mov.b64 %0, {%1, %2};" : "=l"(r) : "f"(lo), "f"(hi));
    return r;
}
__device__ __forceinline__ void fma2(u64& d, u64 a, u64 b) {
    asm("fma.rn.f32x2 %0, %1, %2, %3;" : "=l"(d) : "l"(a), "l"(b), "l"(d));
}
__device__ __forceinline__ void unpack2(u64 v, float& lo, float& hi) {
    asm("mov.b64 {%0, %1}, %2;" : "=f"(lo), "=f"(hi) : "l"(v));
}

// exact branchless elu
__device__ __forceinline__ float elu_f(float x) {
    return fmaxf(x, 0.f) + __expf(fminf(x, 0.f)) - 1.f;
}

// ---------------- scratch ----------------
__device__ float g_buf0[524288];
__device__ float g_buf1[65536];
__device__ float g_buf2[8192];

__host__ __device__ constexpr int smem_floats(int CIN, int S) {
    return 160 * (S + 1)                // hsm: [160][S+1]
         + 2 * (CIN + 10) * 10 * 4      // packed W|U float4 per dir/k/j
         + 2 * 10 * 4                   // packed bias
         + 2 * 20 * 4                   // LSTM2 V
         + 8 + 8                        // LSTM2 R, C
         + S * (8 * CIN + 1);           // padded per-seq x
}

// Thread t: dir = t&1, sequences sA = (t>>1)*2, sB = sA+1 (2 seqs/thread).
// S threads per block handle S sequences.
template <int CIN, int S, int MINB>
__global__ void __launch_bounds__(S, MINB)
agg_kernel(const float* __restrict__ in, float* __restrict__ out,
           const float* __restrict__ wf, const float* __restrict__ uf, const float* __restrict__ bf,
           const float* __restrict__ wb, const float* __restrict__ ub, const float* __restrict__ bb,
           const float* __restrict__ v2f, const float* __restrict__ r2f, const float* __restrict__ c2f,
           const float* __restrict__ v2b, const float* __restrict__ r2b, const float* __restrict__ c2b)
{
    extern __shared__ float smem[];
    constexpr int KTOT = CIN + 10;
    constexpr int XW = 8 * CIN + 1;
    constexpr int SP = S + 1;

    float*  hsm   = smem;                                // [160][SP]
    float4* sWU   = (float4*)(smem + 160 * SP);          // [2][KTOT][10]
    float4* sBias = sWU + 2 * KTOT * 10;                 // [2][10]
    float4* sV    = sBias + 20;                          // [2][20]
    float4* sRv   = sV + 40;                             // [2]
    float4* sCv   = sRv + 2;                             // [2]
    float*  xs    = (float*)(sCv + 2);                   // [S][XW]

    const int tid = threadIdx.x;

    // ---- stage LSTM1 weights in (unit-pair, gate-pair) float4 layout ----
    for (int i = tid; i < 2 * KTOT * 10; i += S) {
        int d = i / (KTOT * 10);
        int r = i - d * (KTOT * 10);
        int k = r / 10;
        int j = r - k * 10;
        const float* W = (k < CIN) ? (((d == 0) ? wf : wb) + k * 40)
                                   : (((d == 0) ? uf : ub) + (k - CIN) * 40);
        int mp = j >> 1, gp = j & 1;
        int c0 = (2 * gp) * 10 + 2 * mp;
        int c2 = (2 * gp + 1) * 10 + 2 * mp;
        sWU[i] = make_float4(W[c0], W[c0 + 1], W[c2], W[c2 + 1]);
    }
    for (int i = tid; i < 20; i += S) {
        int d = i / 10, j = i % 10;
        const float* B = (d == 0) ? bf : bb;
        int mp = j >> 1, gp = j & 1;
        int c0 = (2 * gp) * 10 + 2 * mp;
        int c2 = (2 * gp + 1) * 10 + 2 * mp;
        sBias[i] = make_float4(B[c0], B[c0 + 1], B[c2], B[c2 + 1]);
    }
    for (int i = tid; i < 40; i += S) {
        int d = i / 20, k = i % 20;
        const float* V = (d == 0) ? v2f : v2b;
        sV[i] = make_float4(V[k * 4 + 0], V[k * 4 + 1], V[k * 4 + 2], V[k * 4 + 3]);
    }
    if (tid < 2) {
        const float* R = (tid == 0) ? r2f : r2b;
        const float* C = (tid == 0) ? c2f : c2b;
        sRv[tid] = make_float4(R[0], R[1], R[2], R[3]);
        sCv[tid] = make_float4(C[0], C[1], C[2], C[3]);
    }

    // ---- stage x (coalesced; grids divide exactly) ----
    {
        long long base = (long long)blockIdx.x * S * (8 * CIN);
        const int total = S * 8 * CIN;
        for (int i = tid; i < total; i += S)
            xs[(i / (8 * CIN)) * XW + (i % (8 * CIN))] = in[base + i];
    }
    __syncthreads();

    const int dir = tid & 1;
    const int sA = (tid >> 1) * 2;
    const int sB = sA + 1;
    const float* xA = xs + sA * XW;
    const float* xB = xs + sB * XW;
    const float4* WU = sWU + dir * KTOT * 10;
    const float4* Bv = sBias + dir * 10;

    // ================= LSTM1: one direction, two sequences =================
    {
        float hA[10], cA[10], hB[10], cB[10];
#pragma unroll
        for (int m = 0; m < 10; m++) { hA[m] = 0.f; cA[m] = 0.f; hB[m] = 0.f; cB[m] = 0.f; }

        for (int s = 0; s < 8; s++) {
            const int t = dir ? (7 - s) : s;
            u64 aA[20], aB[20];
#pragma unroll
            for (int j = 0; j < 10; j++) {
                ulonglong2 bq = *(const ulonglong2*)&Bv[j];
                int p = (j >> 1) * 4 + 2 * (j & 1);
                aA[p] = bq.x; aA[p + 1] = bq.y;
                aB[p] = bq.x; aB[p + 1] = bq.y;
            }
#pragma unroll
            for (int k = 0; k < CIN; k++) {
                u64 pA = pack2(xA[t * CIN + k]);
                u64 pB = pack2(xB[t * CIN + k]);
#pragma unroll
                for (int j = 0; j < 10; j++) {
                    ulonglong2 wq = *(const ulonglong2*)&WU[k * 10 + j];
                    int p = (j >> 1) * 4 + 2 * (j & 1);
                    fma2(aA[p], pA, wq.x);
                    fma2(aA[p + 1], pA, wq.y);
                    fma2(aB[p], pB, wq.x);
                    fma2(aB[p + 1], pB, wq.y);
                }
            }
#pragma unroll
            for (int k = 0; k < 10; k++) {
                u64 pA = pack2(hA[k]);
                u64 pB = pack2(hB[k]);
#pragma unroll
                for (int j = 0; j < 10; j++) {
                    ulonglong2 wq = *(const ulonglong2*)&WU[(CIN + k) * 10 + j];
                    int p = (j >> 1) * 4 + 2 * (j & 1);
                    fma2(aA[p], pA, wq.x);
                    fma2(aA[p + 1], pA, wq.y);
                    fma2(aB[p], pB, wq.x);
                    fma2(aB[p + 1], pB, wq.y);
                }
            }
            // gates i,f,g,o: c = elu(f)*c + elu(i)*elu(g); h = elu(o)*elu(c)
#pragma unroll
            for (int mp = 0; mp < 5; mp++) {
                const int m0 = 2 * mp;
                {
                    float i0, i1, f0, f1, g0, g1, o0, o1;
                    unpack2(aA[mp * 4 + 0], i0, i1);
                    unpack2(aA[mp * 4 + 1], f0, f1);
                    unpack2(aA[mp * 4 + 2], g0, g1);
                    unpack2(aA[mp * 4 + 3], o0, o1);
                    cA[m0]     = elu_f(f0) * cA[m0]     + elu_f(i0) * elu_f(g0);
                    cA[m0 + 1] = elu_f(f1) * cA[m0 + 1] + elu_f(i1) * elu_f(g1);
                    float hh0 = elu_f(o0) * elu_f(cA[m0]);
                    float hh1 = elu_f(o1) * elu_f(cA[m0 + 1]);
                    hA[m0] = hh0; hA[m0 + 1] = hh1;
                    hsm[(dir * 80 + t * 10 + m0) * SP + sA]     = hh0;
                    hsm[(dir * 80 + t * 10 + m0 + 1) * SP + sA] = hh1;
                }
                {
                    float i0, i1, f0, f1, g0, g1, o0, o1;
                    unpack2(aB[mp * 4 + 0], i0, i1);
                    unpack2(aB[mp * 4 + 1], f0, f1);
                    unpack2(aB[mp * 4 + 2], g0, g1);
                    unpack2(aB[mp * 4 + 3], o0, o1);
                    cB[m0]     = elu_f(f0) * cB[m0]     + elu_f(i0) * elu_f(g0);
                    cB[m0 + 1] = elu_f(f1) * cB[m0 + 1] + elu_f(i1) * elu_f(g1);
                    float hh0 = elu_f(o0) * elu_f(cB[m0]);
                    float hh1 = elu_f(o1) * elu_f(cB[m0 + 1]);
                    hB[m0] = hh0; hB[m0 + 1] = hh1;
                    hsm[(dir * 80 + t * 10 + m0) * SP + sB]     = hh0;
                    hsm[(dir * 80 + t * 10 + m0 + 1) * SP + sB] = hh1;
                }
            }
        }
    }
    __syncthreads();

    // ========= LSTM2 (H=1): y[t] = bias + V^T h1[t] precompute, short recurrence =========
    const ulonglong2 rq = *(const ulonglong2*)&sRv[dir];
    const ulonglong2 cq = *(const ulonglong2*)&sCv[dir];
    const float4* V = sV + dir * 20;
    const float* colA = hsm + sA;
    const float* colB = hsm + sB;

    u64 yA0[8], yA1[8], yB0[8], yB1[8];
#pragma unroll
    for (int t = 0; t < 8; t++) { yA0[t] = cq.x; yA1[t] = cq.y; yB0[t] = cq.x; yB1[t] = cq.y; }

#pragma unroll 1
    for (int k = 0; k < 20; k++) {          // fwd (k<10) then bwd (k>=10) features
        ulonglong2 vq = *(const ulonglong2*)&V[k];
        const int off = (k < 10) ? k : (70 + k);  // 80 + (k-10)
#pragma unroll
        for (int t = 0; t < 8; t++) {
            u64 a = pack2(colA[(t * 10 + off) * SP]);
            u64 b = pack2(colB[(t * 10 + off) * SP]);
            fma2(yA0[t], a, vq.x); fma2(yA1[t], a, vq.y);
            fma2(yB0[t], b, vq.x); fma2(yB1[t], b, vq.y);
        }
    }

    float h2A = 0.f, c2A = 0.f, h2B = 0.f, c2B = 0.f;
#define REC_STEP(T)                                                         \
    {                                                                       \
        u64 zA0 = yA0[T], zA1 = yA1[T], zB0 = yB0[T], zB1 = yB1[T];         \
        u64 ha = pack2(h2A), hb = pack2(h2B);                               \
        fma2(zA0, ha, rq.x); fma2(zA1, ha, rq.y);                           \
        fma2(zB0, hb, rq.x); fma2(zB1, hb, rq.y);                           \
        float z0, z1, z2, z3;                                               \
        unpack2(zA0, z0, z1); unpack2(zA1, z2, z3);                         \
        c2A = elu_f(z1) * c2A + elu_f(z0) * z2;                             \
        h2A = elu_f(z3) * c2A;                                              \
        unpack2(zB0, z0, z1); unpack2(zB1, z2, z3);                         \
        c2B = elu_f(z1) * c2B + elu_f(z0) * z2;                             \
        h2B = elu_f(z3) * c2B;                                              \
    }
    if (dir == 0) {
        REC_STEP(0) REC_STEP(1) REC_STEP(2) REC_STEP(3)
        REC_STEP(4) REC_STEP(5) REC_STEP(6) REC_STEP(7)
    } else {
        REC_STEP(7) REC_STEP(6) REC_STEP(5) REC_STEP(4)
        REC_STEP(3) REC_STEP(2) REC_STEP(1) REC_STEP(0)
    }
#undef REC_STEP

    // combine fwd/bwd across the thread pair
    u64 mine = pack2f(h2A, h2B);
    u64 other = __shfl_xor_sync(0xFFFFFFFFu, mine, 1);
    if (dir == 0) {
        float oA, oB;
        unpack2(other, oA, oB);
        float mA = 0.5f * (h2A + oA);
        float mB = 0.5f * (h2B + oB);
        out[blockIdx.x * S + sA] = 1.f / (1.f + __expf(-mA));
        out[blockIdx.x * S + sB] = 1.f / (1.f + __expf(-mB));
    }
}

extern "C" void kernel_launch(void* const* d_in, const int* in_sizes, int n_in,
                              void* d_out, int out_size)
{
    const float* x   = (const float*)d_in[0];
    const float* w0f = (const float*)d_in[1];
    const float* u0f = (const float*)d_in[2];
    const float* b0f = (const float*)d_in[3];
    const float* w0b = (const float*)d_in[4];
    const float* u0b = (const float*)d_in[5];
    const float* b0b = (const float*)d_in[6];
    const float* w1f = (const float*)d_in[7];
    const float* u1f = (const float*)d_in[8];
    const float* b1f = (const float*)d_in[9];
    const float* w1b = (const float*)d_in[10];
    const float* u1b = (const float*)d_in[11];
    const float* b1b = (const float*)d_in[12];
    const float* vF  = (const float*)d_in[13];
    const float* rF  = (const float*)d_in[14];
    const float* cF  = (const float*)d_in[15];
    const float* vB  = (const float*)d_in[16];
    const float* rB  = (const float*)d_in[17];
    const float* cB  = (const float*)d_in[18];
    float* out = (float*)d_out;

    float *buf0, *buf1, *buf2;
    cudaGetSymbolAddress((void**)&buf0, g_buf0);
    cudaGetSymbolAddress((void**)&buf1, g_buf1);
    cudaGetSymbolAddress((void**)&buf2, g_buf2);

    const size_t smem5_128 = (size_t)smem_floats(5, 128) * sizeof(float);
    const size_t smem1_128 = (size_t)smem_floats(1, 128) * sizeof(float);
    const size_t smem1_32  = (size_t)smem_floats(1, 32) * sizeof(float);

    void (*k5_128)(const float*, float*, const float*, const float*, const float*,
                   const float*, const float*, const float*, const float*, const float*,
                   const float*, const float*, const float*, const float*) = agg_kernel<5, 128, 2>;
    void (*k1_128)(const float*, float*, const float*, const float*, const float*,
                   const float*, const float*, const float*, const float*, const float*,
                   const float*, const float*, const float*, const float*) = agg_kernel<1, 128, 2>;
    void (*k1_32)(const float*, float*, const float*, const float*, const float*,
                  const float*, const float*, const float*, const float*, const float*,
                  const float*, const float*, const float*, const float*) = agg_kernel<1, 32, 6>;

    cudaFuncSetAttribute(k5_128, cudaFuncAttributeMaxDynamicSharedMemorySize, (int)smem5_128);
    cudaFuncSetAttribute(k1_128, cudaFuncAttributeMaxDynamicSharedMemorySize, (int)smem1_128);
    cudaFuncSetAttribute(k1_32,  cudaFuncAttributeMaxDynamicSharedMemorySize, (int)smem1_32);

    // level 0: x[16,262144,5] -> buf0[524288]
    k5_128<<<524288 / 128, 128, smem5_128>>>(
        x, buf0,
        w0f, u0f, b0f, w0b, u0b, b0b,
        vF, rF, cF, vB, rB, cB);

    // level 1: buf0 -> buf1[65536]
    k1_128<<<65536 / 128, 128, smem1_128>>>(
        buf0, buf1,
        w1f + 0 * 40, u1f + 0 * 400, b1f + 0 * 40,
        w1b + 0 * 40, u1b + 0 * 400, b1b + 0 * 40,
        vF + 1 * 80, rF + 1 * 4, cF + 1 * 4,
        vB + 1 * 80, rB + 1 * 4, cB + 1 * 4);

    // level 2: buf1 -> buf2[8192]
    k1_32<<<8192 / 32, 32, smem1_32>>>(
        buf1, buf2,
        w1f + 1 * 40, u1f + 1 * 400, b1f + 1 * 40,
        w1b + 1 * 40, u1b + 1 * 400, b1b + 1 * 40,
        vF + 2 * 80, rF + 2 * 4, cF + 2 * 4,
        vB + 2 * 80, rB + 2 * 4, cB + 2 * 4);

    // level 3: buf2 -> out[1024]
    k1_32<<<1024 / 32, 32, smem1_32>>>(
        buf2, out,
        w1f + 2 * 40, u1f + 2 * 400, b1f + 2 * 40,
        w1b + 2 * 40, u1b + 2 * 400, b1b + 2 * 40,
        vF + 3 * 80, rF + 3 * 4, cF + 3 * 4,
        vB + 3 * 80, rB + 3 * 4, cB + 3 * 4);
}

// round 5
// speedup vs baseline: 1.0518x; 1.0518x over previous
#include <cuda_runtime.h>
#include <cuda_fp16.h>

typedef unsigned long long u64;

// ---------------- f32x2 helpers (sm_100+) ----------------
__device__ __forceinline__ u64 pack2(float x) {
    u64 r;
    asm("mov.b64 %0, {%1, %1};" : "=l"(r) : "f"(x));
    return r;
}
__device__ __forceinline__ u64 pack2f(float lo, float hi) {
    u64 r;
    asm("mov.b64 %0, {%1, %2};" : "=l"(r) : "f"(lo), "f"(hi));
    return r;
}
__device__ __forceinline__ void fma2(u64& d, u64 a, u64 b) {
    asm("fma.rn.f32x2 %0, %1, %2, %3;" : "=l"(d) : "l"(a), "l"(b), "l"(d));
}
__device__ __forceinline__ u64 fma2_3(u64 a, u64 b, u64 c) {
    u64 d;
    asm("fma.rn.f32x2 %0, %1, %2, %3;" : "=l"(d) : "l"(a), "l"(b), "l"(c));
    return d;
}
__device__ __forceinline__ u64 mul2_(u64 a, u64 b) {
    u64 d; asm("mul.rn.f32x2 %0, %1, %2;" : "=l"(d) : "l"(a), "l"(b)); return d;
}
__device__ __forceinline__ u64 add2_(u64 a, u64 b) {
    u64 d; asm("add.rn.f32x2 %0, %1, %2;" : "=l"(d) : "l"(a), "l"(b)); return d;
}
__device__ __forceinline__ u64 sub2_(u64 a, u64 b) {
    u64 d; asm("sub.rn.f32x2 %0, %1, %2;" : "=l"(d) : "l"(a), "l"(b)); return d;
}
__device__ __forceinline__ void unpack2(u64 v, float& lo, float& hi) {
    asm("mov.b64 {%0, %1}, %2;" : "=f"(lo), "=f"(hi) : "l"(v));
}

// packed exact elu on a unit-pair: elu(x) = max(x,0) + exp(min(x,0)) - 1
//   m = min(x,0) (2x FMNMX); p = x - m (= max(x,0), packed sub);
//   e = exp(m) via EX2 (packed mul by log2e, 2x MUFU); r = (e + p) - 1 (packed)
__device__ __forceinline__ u64 elu2(u64 v) {
    float lo, hi; unpack2(v, lo, hi);
    u64 m = pack2f(fminf(lo, 0.f), fminf(hi, 0.f));
    u64 s = mul2_(m, 0x3FB8AA3B3FB8AA3BULL);   // * log2(e) packed
    float sl, sh; unpack2(s, sl, sh);
    float el, eh;
    asm("ex2.approx.f32 %0, %1;" : "=f"(el) : "f"(sl));
    asm("ex2.approx.f32 %0, %1;" : "=f"(eh) : "f"(sh));
    u64 e = pack2f(el, eh);
    u64 p = sub2_(v, m);
    return add2_(add2_(e, p), 0xBF800000BF800000ULL);  // -1 packed
}

// scalar exact elu (recurrence o-gate, small use)
__device__ __forceinline__ float elu_f(float x) {
    return fmaxf(x, 0.f) + __expf(fminf(x, 0.f)) - 1.f;
}

// ---------------- scratch ----------------
__device__ float g_buf0[524288];
__device__ float g_buf1[65536];
__device__ float g_buf2[8192];

// smem layout (units of float words):
//   hsm (half2): 80 rows x SP cols  -> 80*SP words
//   sWU: 2*KTOT*10 float4; sBias: 20 float4; sV: 40 float4; sR/sC: 2+2 float4
//   xs: S * XW floats
__host__ __device__ constexpr int smem_floats(int CIN, int S) {
    return 80 * (S + 1)
         + 2 * (CIN + 10) * 10 * 4
         + 20 * 4 + 40 * 4 + 16
         + S * (8 * CIN + 1);
}

// Thread t: dir = t&1, sequences sA = (t>>1)*2, sB = sA+1 (2 seqs/thread, one dir).
template <int CIN, int S, int MINB>
__global__ void __launch_bounds__(S, MINB)
agg_kernel(const float* __restrict__ in, float* __restrict__ out,
           const float* __restrict__ wf, const float* __restrict__ uf, const float* __restrict__ bf,
           const float* __restrict__ wb, const float* __restrict__ ub, const float* __restrict__ bb,
           const float* __restrict__ v2f, const float* __restrict__ r2f, const float* __restrict__ c2f,
           const float* __restrict__ v2b, const float* __restrict__ r2b, const float* __restrict__ c2b)
{
    extern __shared__ float smem[];
    constexpr int KTOT = CIN + 10;
    constexpr int XW = 8 * CIN + 1;
    constexpr int SP = S + 1;

    __half2* hsm2  = (__half2*)smem;                       // [80][SP] half2
    float4*  sWU   = (float4*)(smem + 80 * SP);            // [2][KTOT][10]
    float4*  sBias = sWU + 2 * KTOT * 10;                  // [2][10]
    float4*  sV    = sBias + 20;                           // [2][20]
    float4*  sRv   = sV + 40;                              // [2]
    float4*  sCv   = sRv + 2;                              // [2]
    float*   xs    = (float*)(sCv + 2);                    // [S][XW]

    const int tid = threadIdx.x;

    // ---- stage LSTM1 weights in (unit-pair, gate-pair) float4 layout ----
    for (int i = tid; i < 2 * KTOT * 10; i += S) {
        int d = i / (KTOT * 10);
        int r = i - d * (KTOT * 10);
        int k = r / 10;
        int j = r - k * 10;
        const float* W = (k < CIN) ? (((d == 0) ? wf : wb) + k * 40)
                                   : (((d == 0) ? uf : ub) + (k - CIN) * 40);
        int mp = j >> 1, gp = j & 1;
        int c0 = (2 * gp) * 10 + 2 * mp;
        int c2 = (2 * gp + 1) * 10 + 2 * mp;
        sWU[i] = make_float4(W[c0], W[c0 + 1], W[c2], W[c2 + 1]);
    }
    for (int i = tid; i < 20; i += S) {
        int d = i / 10, j = i % 10;
        const float* B = (d == 0) ? bf : bb;
        int mp = j >> 1, gp = j & 1;
        int c0 = (2 * gp) * 10 + 2 * mp;
        int c2 = (2 * gp + 1) * 10 + 2 * mp;
        sBias[i] = make_float4(B[c0], B[c0 + 1], B[c2], B[c2 + 1]);
    }
    for (int i = tid; i < 40; i += S) {
        int d = i / 20, k = i % 20;
        const float* V = (d == 0) ? v2f : v2b;
        sV[i] = make_float4(V[k * 4 + 0], V[k * 4 + 1], V[k * 4 + 2], V[k * 4 + 3]);
    }
    if (tid < 2) {
        const float* R = (tid == 0) ? r2f : r2b;
        const float* C = (tid == 0) ? c2f : c2b;
        sRv[tid] = make_float4(R[0], R[1], R[2], R[3]);
        sCv[tid] = make_float4(C[0], C[1], C[2], C[3]);
    }

    // ---- stage x (coalesced; grids divide exactly) ----
    {
        long long base = (long long)blockIdx.x * S * (8 * CIN);
        const int total = S * 8 * CIN;
        for (int i = tid; i < total; i += S)
            xs[(i / (8 * CIN)) * XW + (i % (8 * CIN))] = in[base + i];
    }
    __syncthreads();

    const int dir = tid & 1;
    const int sA = (tid >> 1) * 2;
    const int sB = sA + 1;
    const float* xA = xs + sA * XW;
    const float* xB = xs + sB * XW;
    const float4* WU = sWU + dir * KTOT * 10;
    const float4* Bv = sBias + dir * 10;

    // ================= LSTM1: one direction, two sequences, packed gates =================
    {
        u64 hA[5], cA[5], hB[5], cB[5];   // unit pairs, packed f32x2
#pragma unroll
        for (int m = 0; m < 5; m++) { hA[m] = 0ULL; cA[m] = 0ULL; hB[m] = 0ULL; cB[m] = 0ULL; }

#pragma unroll 1
        for (int s = 0; s < 8; s++) {
            const int t = dir ? (7 - s) : s;
            u64 aA[20], aB[20];           // acc[mp*4+g] = gate g of units (2mp, 2mp+1)
#pragma unroll
            for (int j = 0; j < 10; j++) {
                ulonglong2 bq = *(const ulonglong2*)&Bv[j];
                int p = (j >> 1) * 4 + 2 * (j & 1);
                aA[p] = bq.x; aA[p + 1] = bq.y;
                aB[p] = bq.x; aB[p + 1] = bq.y;
            }
#pragma unroll
            for (int k = 0; k < CIN; k++) {
                u64 pA = pack2(xA[t * CIN + k]);
                u64 pB = pack2(xB[t * CIN + k]);
#pragma unroll
                for (int j = 0; j < 10; j++) {
                    ulonglong2 wq = *(const ulonglong2*)&WU[k * 10 + j];
                    int p = (j >> 1) * 4 + 2 * (j & 1);
                    fma2(aA[p], pA, wq.x);
                    fma2(aA[p + 1], pA, wq.y);
                    fma2(aB[p], pB, wq.x);
                    fma2(aB[p + 1], pB, wq.y);
                }
            }
#pragma unroll
            for (int kp = 0; kp < 5; kp++) {
                float a0, a1, b0, b1;
                unpack2(hA[kp], a0, a1);
                unpack2(hB[kp], b0, b1);
#pragma unroll
                for (int sub = 0; sub < 2; sub++) {
                    const int k = kp * 2 + sub;
                    u64 pA = pack2(sub ? a1 : a0);
                    u64 pB = pack2(sub ? b1 : b0);
#pragma unroll
                    for (int j = 0; j < 10; j++) {
                        ulonglong2 wq = *(const ulonglong2*)&WU[(CIN + k) * 10 + j];
                        int p = (j >> 1) * 4 + 2 * (j & 1);
                        fma2(aA[p], pA, wq.x);
                        fma2(aA[p + 1], pA, wq.y);
                        fma2(aB[p], pB, wq.x);
                        fma2(aB[p + 1], pB, wq.y);
                    }
                }
            }
            // packed gates: c = elu2(f)*c + elu2(i)*elu2(g); h = elu2(o)*elu2(c)
            __half2* hrow = hsm2 + (dir * 40 + t * 5) * SP;
#pragma unroll
            for (int mp = 0; mp < 5; mp++) {
                {
                    u64 ei = elu2(aA[mp * 4 + 0]);
                    u64 ef = elu2(aA[mp * 4 + 1]);
                    u64 eg = elu2(aA[mp * 4 + 2]);
                    u64 eo = elu2(aA[mp * 4 + 3]);
                    cA[mp] = fma2_3(ef, cA[mp], mul2_(ei, eg));
                    hA[mp] = mul2_(eo, elu2(cA[mp]));
                    float l, h; unpack2(hA[mp], l, h);
                    hrow[mp * SP + sA] = __floats2half2_rn(l, h);
                }
                {
                    u64 ei = elu2(aB[mp * 4 + 0]);
                    u64 ef = elu2(aB[mp * 4 + 1]);
                    u64 eg = elu2(aB[mp * 4 + 2]);
                    u64 eo = elu2(aB[mp * 4 + 3]);
                    cB[mp] = fma2_3(ef, cB[mp], mul2_(ei, eg));
                    hB[mp] = mul2_(eo, elu2(cB[mp]));
                    float l, h; unpack2(hB[mp], l, h);
                    hrow[mp * SP + sB] = __floats2half2_rn(l, h);
                }
            }
        }
    }
    __syncthreads();

    // ========= LSTM2 (H=1): y[t] precompute per seq (sequential), then recurrence =========
    const ulonglong2 rq = *(const ulonglong2*)&sRv[dir];
    const ulonglong2 cq = *(const ulonglong2*)&sCv[dir];
    const float4* V = sV + dir * 20;
    const __half* hsmh = (const __half*)hsm2;

    float h2[2];
#pragma unroll 1
    for (int pass = 0; pass < 2; pass++) {
        const int seqX = (pass == 0) ? sA : sB;
        u64 y0[8], y1[8];
#pragma unroll
        for (int t = 0; t < 8; t++) { y0[t] = cq.x; y1[t] = cq.y; }

#pragma unroll 1
        for (int k = 0; k < 20; k++) {
            ulonglong2 vq = *(const ulonglong2*)&V[k];
            const int d = (k >= 10) ? 1 : 0;
            const int u = k - d * 10;
            const int rowbase = d * 40 + (u >> 1);
            const int half_i = u & 1;
#pragma unroll
            for (int t = 0; t < 8; t++) {
                float hv = __half2float(hsmh[((rowbase + t * 5) * SP + seqX) * 2 + half_i]);
                u64 a = pack2(hv);
                fma2(y0[t], a, vq.x);
                fma2(y1[t], a, vq.y);
            }
        }

        float hh = 0.f, cc = 0.f;
#define REC_STEP(T)                                                  \
        {                                                            \
            u64 z0 = y0[T], z1 = y1[T];                              \
            u64 a = pack2(hh);                                       \
            fma2(z0, a, rq.x); fma2(z1, a, rq.y);                    \
            u64 e01 = elu2(z0);                                      \
            float ei, ef; unpack2(e01, ei, ef);                      \
            float zg, zo; unpack2(z1, zg, zo);                       \
            cc = ef * cc + ei * zg;                                  \
            hh = elu_f(zo) * cc;                                     \
        }
        if (dir == 0) {
            REC_STEP(0) REC_STEP(1) REC_STEP(2) REC_STEP(3)
            REC_STEP(4) REC_STEP(5) REC_STEP(6) REC_STEP(7)
        } else {
            REC_STEP(7) REC_STEP(6) REC_STEP(5) REC_STEP(4)
            REC_STEP(3) REC_STEP(2) REC_STEP(1) REC_STEP(0)
        }
#undef REC_STEP
        h2[pass] = hh;
    }

    // combine fwd/bwd across the thread pair
    u64 mine = pack2f(h2[0], h2[1]);
    u64 other = __shfl_xor_sync(0xFFFFFFFFu, mine, 1);
    if (dir == 0) {
        float oA, oB;
        unpack2(other, oA, oB);
        float mA = 0.5f * (h2[0] + oA);
        float mB = 0.5f * (h2[1] + oB);
        out[blockIdx.x * S + sA] = 1.f / (1.f + __expf(-mA));
        out[blockIdx.x * S + sB] = 1.f / (1.f + __expf(-mB));
    }
}

extern "C" void kernel_launch(void* const* d_in, const int* in_sizes, int n_in,
                              void* d_out, int out_size)
{
    const float* x   = (const float*)d_in[0];
    const float* w0f = (const float*)d_in[1];
    const float* u0f = (const float*)d_in[2];
    const float* b0f = (const float*)d_in[3];
    const float* w0b = (const float*)d_in[4];
    const float* u0b = (const float*)d_in[5];
    const float* b0b = (const float*)d_in[6];
    const float* w1f = (const float*)d_in[7];
    const float* u1f = (const float*)d_in[8];
    const float* b1f = (const float*)d_in[9];
    const float* w1b = (const float*)d_in[10];
    const float* u1b = (const float*)d_in[11];
    const float* b1b = (const float*)d_in[12];
    const float* vF  = (const float*)d_in[13];
    const float* rF  = (const float*)d_in[14];
    const float* cF  = (const float*)d_in[15];
    const float* vB  = (const float*)d_in[16];
    const float* rB  = (const float*)d_in[17];
    const float* cB  = (const float*)d_in[18];
    float* out = (float*)d_out;

    float *buf0, *buf1, *buf2;
    cudaGetSymbolAddress((void**)&buf0, g_buf0);
    cudaGetSymbolAddress((void**)&buf1, g_buf1);
    cudaGetSymbolAddress((void**)&buf2, g_buf2);

    const size_t smem5_128 = (size_t)smem_floats(5, 128) * sizeof(float);
    const size_t smem1_128 = (size_t)smem_floats(1, 128) * sizeof(float);
    const size_t smem1_32  = (size_t)smem_floats(1, 32) * sizeof(float);

    void (*k5_128)(const float*, float*, const float*, const float*, const float*,
                   const float*, const float*, const float*, const float*, const float*,
                   const float*, const float*, const float*, const float*) = agg_kernel<5, 128, 3>;
    void (*k1_128)(const float*, float*, const float*, const float*, const float*,
                   const float*, const float*, const float*, const float*, const float*,
                   const float*, const float*, const float*, const float*) = agg_kernel<1, 128, 3>;
    void (*k1_32)(const float*, float*, const float*, const float*, const float*,
                  const float*, const float*, const float*, const float*, const float*,
                  const float*, const float*, const float*, const float*) = agg_kernel<1, 32, 8>;

    cudaFuncSetAttribute(k5_128, cudaFuncAttributeMaxDynamicSharedMemorySize, (int)smem5_128);
    cudaFuncSetAttribute(k1_128, cudaFuncAttributeMaxDynamicSharedMemorySize, (int)smem1_128);
    cudaFuncSetAttribute(k1_32,  cudaFuncAttributeMaxDynamicSharedMemorySize, (int)smem1_32);

    // level 0: x[16,262144,5] -> buf0[524288]
    k5_128<<<524288 / 128, 128, smem5_128>>>(
        x, buf0,
        w0f, u0f, b0f, w0b, u0b, b0b,
        vF, rF, cF, vB, rB, cB);

    // level 1: buf0 -> buf1[65536]
    k1_128<<<65536 / 128, 128, smem1_128>>>(
        buf0, buf1,
        w1f + 0 * 40, u1f + 0 * 400, b1f + 0 * 40,
        w1b + 0 * 40, u1b + 0 * 400, b1b + 0 * 40,
        vF + 1 * 80, rF + 1 * 4, cF + 1 * 4,
        vB + 1 * 80, rB + 1 * 4, cB + 1 * 4);

    // level 2: buf1 -> buf2[8192]
    k1_32<<<8192 / 32, 32, smem1_32>>>(
        buf1, buf2,
        w1f + 1 * 40, u1f + 1 * 400, b1f + 1 * 40,
        w1b + 1 * 40, u1b + 1 * 400, b1b + 1 * 40,
        vF + 2 * 80, rF + 2 * 4, cF + 2 * 4,
        vB + 2 * 80, rB + 2 * 4, cB + 2 * 4);

    // level 3: buf2 -> out[1024]
    k1_32<<<1024 / 32, 32, smem1_32>>>(
        buf2, out,
        w1f + 2 * 40, u1f + 2 * 400, b1f + 2 * 40,
        w1b + 2 * 40, u1b + 2 * 400, b1b + 2 * 40,
        vF + 3 * 80, rF + 3 * 4, cF + 3 * 4,
        vB + 3 * 80, rB + 3 * 4, cB + 3 * 4);
}